// round 5
// baseline (speedup 1.0000x reference)
#include <cuda_runtime.h>
#include <cuda_bf16.h>
#include <stdint.h>

#define D_    64
#define NROW  16384
#define KCB   8192
#define BM    128
#define BN    256
#define NT    256
#define KT    (KCB / BN)     // 32
#define CAP   256

// smem layout (bytes): A 16KB | W 2x32KB | wsq 2x1KB
#define SM_A    0
#define SM_W    16384
#define SM_WSQ  81920
#define SMEM_BYTES 83968

__device__ float    g_xsq[NROW];
__device__ float    g_wsq[KCB];
__device__ float    g_wmax;
__device__ uint32_t g_xbf[NROW * 32];   // bf16x2: row r, k-pair kp at [r*32+kp]
__device__ uint32_t g_wbf[KCB * 32];
__device__ int      g_cnt[NROW];
__device__ int      g_cand[NROW * CAP];
__device__ float    g_rowloss[NROW];

// ---------------------------------------------------------------------------
__device__ __forceinline__ uint32_t smem_u32(const void* p) {
    uint32_t a;
    asm("{ .reg .u64 t; cvta.to.shared.u64 t, %1; cvt.u32.u64 %0, t; }" : "=r"(a) : "l"(p));
    return a;
}
__device__ __forceinline__ void cp16(uint32_t dst, const void* src) {
    asm volatile("cp.async.cg.shared.global [%0], [%1], 16;" :: "r"(dst), "l"(src));
}
__device__ __forceinline__ void cp_commit() { asm volatile("cp.async.commit_group;"); }
__device__ __forceinline__ void cp_wait1()  { asm volatile("cp.async.wait_group 1;"); }
__device__ __forceinline__ void cp_wait0()  { asm volatile("cp.async.wait_group 0;"); }

__device__ __forceinline__ void ldsm4(uint32_t (&r)[4], uint32_t addr) {
    asm volatile("ldmatrix.sync.aligned.m8n8.x4.shared.b16 {%0,%1,%2,%3}, [%4];"
        : "=r"(r[0]), "=r"(r[1]), "=r"(r[2]), "=r"(r[3]) : "r"(addr));
}
__device__ __forceinline__ void mma_bf16(float (&c)[4], const uint32_t (&a)[4],
                                         uint32_t b0, uint32_t b1) {
    asm volatile(
        "mma.sync.aligned.m16n8k16.row.col.f32.bf16.bf16.f32 "
        "{%0,%1,%2,%3},{%4,%5,%6,%7},{%8,%9},{%0,%1,%2,%3};"
        : "+f"(c[0]), "+f"(c[1]), "+f"(c[2]), "+f"(c[3])
        : "r"(a[0]), "r"(a[1]), "r"(a[2]), "r"(a[3]), "r"(b0), "r"(b1));
}

// row-of-128B tile, XOR swizzle on 16B chunks
__device__ __forceinline__ uint32_t swz(int row, int qb) {
    return (uint32_t)(row * 128 + (qb ^ ((row & 7) * 16)));
}

// ---------------------------------------------------------------------------
// prep: warp-per-row norms + bf16 conversion + counter reset
// ---------------------------------------------------------------------------
__global__ __launch_bounds__(256) void prep_kernel(const float* __restrict__ x,
                                                   const float* __restrict__ w) {
    int gw = (blockIdx.x * 256 + threadIdx.x) >> 5;
    int lane = threadIdx.x & 31;
    if (gw < NROW) {
        float2 v = ((const float2*)(x + (size_t)gw * D_))[lane];
        float s = v.x * v.x + v.y * v.y;
#pragma unroll
        for (int o = 16; o > 0; o >>= 1) s += __shfl_xor_sync(0xffffffffu, s, o);
        __nv_bfloat162 h = __float22bfloat162_rn(v);
        g_xbf[gw * 32 + lane] = *reinterpret_cast<uint32_t*>(&h);
        if (lane == 0) g_xsq[gw] = s;
        if (lane == 1) g_cnt[gw] = 0;
    } else if (gw < NROW + KCB) {
        int r = gw - NROW;
        float2 v = ((const float2*)(w + (size_t)r * D_))[lane];
        float s = v.x * v.x + v.y * v.y;
#pragma unroll
        for (int o = 16; o > 0; o >>= 1) s += __shfl_xor_sync(0xffffffffu, s, o);
        __nv_bfloat162 h = __float22bfloat162_rn(v);
        g_wbf[r * 32 + lane] = *reinterpret_cast<uint32_t*>(&h);
        if (lane == 0) g_wsq[r] = s;
    }
}

__global__ void wmax_kernel() {
    __shared__ float sm[256];
    float m = 0.f;
    for (int i = threadIdx.x; i < KCB; i += 256) m = fmaxf(m, g_wsq[i]);
    sm[threadIdx.x] = m;
    __syncthreads();
    for (int o = 128; o > 0; o >>= 1) {
        if (threadIdx.x < o) sm[threadIdx.x] = fmaxf(sm[threadIdx.x], sm[threadIdx.x + o]);
        __syncthreads();
    }
    if (threadIdx.x == 0) g_wmax = sm[0];
}

// ---------------------------------------------------------------------------
// vq_mma: bf16 m16n8k16 distance GEMM + fused candidate filter
// block tile 128x256, 8 warps (2m x 4n), warp tile 64x64 in two 32-col halves
// ---------------------------------------------------------------------------
__global__ __launch_bounds__(NT, 1) void vq_mma() {
    extern __shared__ __align__(128) char smem_raw[];
    const uint32_t sbase = smem_u32(smem_raw);
    const int tid = threadIdx.x, lane = tid & 31, wid = tid >> 5;
    const int wm = wid >> 2, wn = wid & 3;
    const int rowBase = blockIdx.x * BM;

    // ---- A tile: 128 rows x 128B (bf16), swizzled ----
#pragma unroll
    for (int i = 0; i < 4; i++) {
        int idx = tid + i * NT;
        int r = idx >> 3, q = idx & 7;
        cp16(sbase + SM_A + swz(r, q * 16), g_xbf + (size_t)(rowBase + r) * 32 + q * 4);
    }

    auto issue_tile = [&](int t, int b) {
#pragma unroll
        for (int i = 0; i < 8; i++) {
            int idx = tid + i * NT;
            int r = idx >> 3, q = idx & 7;
            cp16(sbase + SM_W + b * 32768 + swz(r, q * 16),
                 g_wbf + ((size_t)t * BN + r) * 32 + q * 4);
        }
        if (tid < 64) cp16(sbase + SM_WSQ + b * 1024 + tid * 16, g_wsq + t * BN + tid * 4);
    };

    issue_tile(0, 0);
    cp_commit();

    // ---- per-thread row state: 8 rows (mf x hi) ----
    float xq[8], bnd[8], gmin[8];
    int rowid[8];
    const float bndc = 0.0625f * sqrtf(g_wmax);   // 2^-4 * ||w||max
#pragma unroll
    for (int mf = 0; mf < 4; mf++)
#pragma unroll
        for (int hi = 0; hi < 2; hi++) {
            int s = mf * 2 + hi;
            int r = rowBase + wm * 64 + mf * 16 + (lane >> 2) + hi * 8;
            rowid[s] = r;
            float q = g_xsq[r];
            xq[s] = q;
            bnd[s] = bndc * sqrtf(q);
            gmin[s] = 1e30f;
        }

    // fragment address components (lane-constant)
    const int aRow = wm * 64 + (lane & 7) + ((lane >> 3) & 1) * 8;
    const int aByteSel = ((lane >> 4) & 1) * 16;
    const int bRowOff = (lane & 7) + ((lane >> 4) & 1) * 8;
    const int bByteSel = ((lane >> 3) & 1) * 16;
    const uint32_t lswz = (uint32_t)((lane & 7) * 16);

    for (int t = 0; t < KT; t++) {
        const int buf = t & 1;
        if (t + 1 < KT) { issue_tile(t + 1, (t + 1) & 1); cp_commit(); cp_wait1(); }
        else            { cp_wait0(); }
        __syncthreads();

        const float* wsqS = (const float*)(smem_raw + SM_WSQ + buf * 1024);
        const uint32_t wbase = sbase + SM_W + buf * 32768;

#pragma unroll
        for (int half = 0; half < 2; half++) {
            float C[4][4][4];
#pragma unroll
            for (int mf = 0; mf < 4; mf++)
#pragma unroll
                for (int nf = 0; nf < 4; nf++)
#pragma unroll
                    for (int q = 0; q < 4; q++) C[mf][nf][q] = 0.f;

#pragma unroll
            for (int ks = 0; ks < 4; ks++) {
                uint32_t a[4][4];
#pragma unroll
                for (int mf = 0; mf < 4; mf++) {
                    int row = aRow + mf * 16;
                    uint32_t byte = (uint32_t)(ks * 32 + aByteSel) ^ lswz;
                    ldsm4(a[mf], sbase + SM_A + row * 128 + byte);
                }
                uint32_t b[2][4];
#pragma unroll
                for (int nf2 = 0; nf2 < 2; nf2++) {
                    int n = wn * 64 + half * 32 + nf2 * 16 + bRowOff;
                    uint32_t byte = (uint32_t)(ks * 32 + bByteSel) ^ lswz;
                    ldsm4(b[nf2], wbase + n * 128 + byte);
                }
#pragma unroll
                for (int mf = 0; mf < 4; mf++) {
                    mma_bf16(C[mf][0], a[mf], b[0][0], b[0][1]);
                    mma_bf16(C[mf][1], a[mf], b[0][2], b[0][3]);
                    mma_bf16(C[mf][2], a[mf], b[1][0], b[1][1]);
                    mma_bf16(C[mf][3], a[mf], b[1][2], b[1][3]);
                }
            }

            // ---- epilogue: distances, running min, candidate append ----
            const int nbase = wn * 64 + half * 32;
#pragma unroll
            for (int nf = 0; nf < 4; nf++) {
                int cw = nbase + nf * 8 + 2 * (lane & 3);
                float wq0 = wsqS[cw], wq1 = wsqS[cw + 1];
                int colb = t * BN + cw;
#pragma unroll
                for (int mf = 0; mf < 4; mf++)
#pragma unroll
                    for (int hi = 0; hi < 2; hi++) {
                        int s = mf * 2 + hi;
                        float d0 = fmaf(-2.f, C[mf][nf][hi * 2 + 0], xq[s] + wq0);
                        float d1 = fmaf(-2.f, C[mf][nf][hi * 2 + 1], xq[s] + wq1);
                        float thr = gmin[s] + bnd[s];
                        if (d0 < thr) {
                            int p = atomicAdd(&g_cnt[rowid[s]], 1);
                            if (p < CAP) g_cand[rowid[s] * CAP + p] = colb;
                        }
                        if (d1 < thr) {
                            int p = atomicAdd(&g_cnt[rowid[s]], 1);
                            if (p < CAP) g_cand[rowid[s] * CAP + p] = colb + 1;
                        }
                        gmin[s] = fminf(gmin[s], fminf(d0, d1));
                    }
            }
        }

        // tighten running min across the 4 lanes sharing each row
#pragma unroll
        for (int s = 0; s < 8; s++) {
            float v = gmin[s];
            v = fminf(v, __shfl_xor_sync(0xffffffffu, v, 1));
            v = fminf(v, __shfl_xor_sync(0xffffffffu, v, 2));
            gmin[s] = v;
        }
        __syncthreads();
    }
}

// ---------------------------------------------------------------------------
// rescore: exact fp32 argmin over candidates (warp per row), tie-break lowest idx
// out: [0]=loss, [1..N*D]=quantized, [1+N*D..]=indices (float)
// ---------------------------------------------------------------------------
__global__ __launch_bounds__(256) void rescore_kernel(const float* __restrict__ x,
                                                      const float* __restrict__ w,
                                                      float* __restrict__ out) {
    int row = (blockIdx.x * 256 + threadIdx.x) >> 5;
    int lane = threadIdx.x & 31;
    if (row >= NROW) return;

    int cnt = g_cnt[row];
    if (cnt > CAP) cnt = CAP;
    const int* cl = g_cand + (size_t)row * CAP;
    float2 xv = ((const float2*)(x + (size_t)row * D_))[lane];

    int bc;
    if (cnt == 1) {
        bc = cl[0];
    } else {
        float xq = g_xsq[row];
        float bd = 3.4e38f;
        bc = 0x7fffffff;
        int i = 0;
        for (; i + 2 <= cnt; i += 2) {
            int c0 = cl[i], c1 = cl[i + 1];
            float2 w0 = ((const float2*)(w + (size_t)c0 * D_))[lane];
            float2 w1 = ((const float2*)(w + (size_t)c1 * D_))[lane];
            float p0 = xv.x * w0.x + xv.y * w0.y;
            float p1 = xv.x * w1.x + xv.y * w1.y;
#pragma unroll
            for (int o = 16; o > 0; o >>= 1) {
                p0 += __shfl_xor_sync(0xffffffffu, p0, o);
                p1 += __shfl_xor_sync(0xffffffffu, p1, o);
            }
            float d0 = xq + g_wsq[c0] - 2.f * p0;
            float d1 = xq + g_wsq[c1] - 2.f * p1;
            if (d0 < bd || (d0 == bd && c0 < bc)) { bd = d0; bc = c0; }
            if (d1 < bd || (d1 == bd && c1 < bc)) { bd = d1; bc = c1; }
        }
        if (i < cnt) {
            int c0 = cl[i];
            float2 w0 = ((const float2*)(w + (size_t)c0 * D_))[lane];
            float p0 = xv.x * w0.x + xv.y * w0.y;
#pragma unroll
            for (int o = 16; o > 0; o >>= 1) p0 += __shfl_xor_sync(0xffffffffu, p0, o);
            float d0 = xq + g_wsq[c0] - 2.f * p0;
            if (d0 < bd || (d0 == bd && c0 < bc)) { bd = d0; bc = c0; }
        }
    }

    float2 wv = ((const float2*)(w + (size_t)bc * D_))[lane];
    float* qo = out + 1 + (size_t)row * D_ + lane * 2;   // 4B-aligned region: scalar stores
    qo[0] = wv.x;
    qo[1] = wv.y;
    if (lane == 0) out[1 + (size_t)NROW * D_ + row] = (float)bc;

    float dx = wv.x - xv.x, dy = wv.y - xv.y;
    float l = dx * dx + dy * dy;
#pragma unroll
    for (int o = 16; o > 0; o >>= 1) l += __shfl_xor_sync(0xffffffffu, l, o);
    if (lane == 0) g_rowloss[row] = l;
}

// ---------------------------------------------------------------------------
__global__ void finalize_kernel(float* __restrict__ out) {
    __shared__ float sm[256];
    float s = 0.f;
    for (int i = threadIdx.x; i < NROW; i += 256) s += g_rowloss[i];
    sm[threadIdx.x] = s;
    __syncthreads();
    for (int o = 128; o > 0; o >>= 1) {
        if (threadIdx.x < o) sm[threadIdx.x] += sm[threadIdx.x + o];
        __syncthreads();
    }
    if (threadIdx.x == 0) out[0] = 1.25f * sm[0] / (float)(NROW * D_);
}

// ---------------------------------------------------------------------------
extern "C" void kernel_launch(void* const* d_in, const int* in_sizes, int n_in,
                              void* d_out, int out_size) {
    const float* x = (const float*)d_in[0];
    const float* w = (const float*)d_in[1];
    float* out = (float*)d_out;

    prep_kernel<<<(NROW + KCB) * 32 / 256, 256>>>(x, w);
    wmax_kernel<<<1, 256>>>();

    cudaFuncSetAttribute(vq_mma, cudaFuncAttributeMaxDynamicSharedMemorySize, SMEM_BYTES);
    vq_mma<<<NROW / BM, NT, SMEM_BYTES>>>();

    rescore_kernel<<<NROW / 8, 256>>>(x, w, out);
    finalize_kernel<<<1, 256>>>(out);
}

// round 6
// speedup vs baseline: 1.0087x; 1.0087x over previous
#include <cuda_runtime.h>
#include <stdint.h>

#define D_    64
#define NROW  16384
#define KCB   8192
#define BM    128
#define BN    128
#define NT    256
#define KT    (KCB / BN)       // 64
#define XPAD  65

// smem layout (float offsets)
#define XS_OFF 0
#define WT_OFF (BM * XPAD)              // 8320
#define WT_SZ  (D_ * BN)                // 8192 per buffer
#define WQ_OFF (WT_OFF + 2 * WT_SZ)     // 24704
#define SMEM_FLOATS (WQ_OFF + 2 * BN)   // 24960
#define SMEM_BYTES  (SMEM_FLOATS * 4)   // 99840

typedef unsigned long long ull;

__device__ float g_xsq[NROW];
__device__ float g_wsq[KCB];
__device__ float g_block_loss[128];

// ---------------------------------------------------------------------------
__device__ __forceinline__ uint32_t smem_u32(const void* p) {
    uint32_t a;
    asm("{ .reg .u64 t; cvta.to.shared.u64 t, %1; cvt.u32.u64 %0, t; }" : "=r"(a) : "l"(p));
    return a;
}
__device__ __forceinline__ void cp4(uint32_t dst, const void* src) {
    asm volatile("cp.async.ca.shared.global [%0], [%1], 4;" :: "r"(dst), "l"(src));
}
__device__ __forceinline__ void cp_commit() { asm volatile("cp.async.commit_group;"); }
__device__ __forceinline__ void cp_wait1()  { asm volatile("cp.async.wait_group 1;"); }
__device__ __forceinline__ void cp_wait0()  { asm volatile("cp.async.wait_group 0;"); }

__device__ __forceinline__ void fma2(ull& c, ull a, ull b) {
    asm("fma.rn.f32x2 %0, %1, %2, %0;" : "+l"(c) : "l"(a), "l"(b));
}
__device__ __forceinline__ ull pack2(float v) {
    ull r;
    uint32_t b = __float_as_uint(v);
    asm("mov.b64 %0, {%1, %2};" : "=l"(r) : "r"(b), "r"(b));
    return r;
}
__device__ __forceinline__ void unpack2(ull v, float& lo, float& hi) {
    uint32_t a, b;
    asm("mov.b64 {%0, %1}, %2;" : "=r"(a), "=r"(b) : "l"(v));
    lo = __uint_as_float(a);
    hi = __uint_as_float(b);
}

// ---------------------------------------------------------------------------
// prep: squared norms
// ---------------------------------------------------------------------------
__global__ void prep_kernel(const float* __restrict__ x, const float* __restrict__ w) {
    int t = blockIdx.x * blockDim.x + threadIdx.x;
    if (t < NROW) {
        const float4* xr = (const float4*)(x + (size_t)t * D_);
        float s = 0.f;
#pragma unroll
        for (int i = 0; i < D_ / 4; i++) {
            float4 v = xr[i];
            s += v.x * v.x + v.y * v.y + v.z * v.z + v.w * v.w;
        }
        g_xsq[t] = s;
    }
    if (t < KCB) {
        const float4* wr = (const float4*)(w + (size_t)t * D_);
        float s = 0.f;
#pragma unroll
        for (int i = 0; i < D_ / 4; i++) {
            float4 v = wr[i];
            s += v.x * v.x + v.y * v.y + v.z * v.z + v.w * v.w;
        }
        g_wsq[t] = s;
    }
}

// ---------------------------------------------------------------------------
// vq_main: exact fp32 argmin-GEMM using packed fma.rn.f32x2
// out: [0]=loss, [1 .. N*D]=quantized, [1+N*D ..]=indices (as float)
// ---------------------------------------------------------------------------
__global__ __launch_bounds__(NT, 1) void vq_main(const float* __restrict__ x,
                                                 const float* __restrict__ w,
                                                 float* __restrict__ out) {
    extern __shared__ float sm[];
    float* xs = sm + XS_OFF;
    const uint32_t sbase = smem_u32(sm);

    const int t = threadIdx.x;
    const int tx = t & 15, ty = t >> 4;
    const int rowBase = blockIdx.x * BM;

    // ---- load x tile: 128 x 64 fp32, pitch 65 (conflict-free scalar reads) ----
#pragma unroll
    for (int i = 0; i < 8; i++) {
        int idx4 = t + i * NT;               // 2048 float4
        int r = idx4 >> 4, q = idx4 & 15;
        float4 v = *(const float4*)(x + (size_t)(rowBase + r) * D_ + q * 4);
        float* p = xs + r * XPAD + q * 4;
        p[0] = v.x; p[1] = v.y; p[2] = v.z; p[3] = v.w;
    }

    // ---- transposed cp.async of codebook tile tt into buffer b ----
    // wsT[d][col] with pair-swizzle: pair p stored at physical (p ^ (d&15))
    auto issue = [&](int tt, int b) {
        const float* wsrc = w + (size_t)tt * BN * D_;
        const uint32_t wbase = sbase + (WT_OFF + b * WT_SZ) * 4;
#pragma unroll
        for (int i = 0; i < 32; i++) {
            int idx = t + i * NT;            // 8192 elements
            int col = idx >> 6, d = idx & 63;
            int phys = ((col >> 1) ^ (d & 15)) * 2 + (col & 1);
            cp4(wbase + (uint32_t)(d * BN + phys) * 4, wsrc + (size_t)col * D_ + d);
        }
        if (t < BN)
            cp4(sbase + (WQ_OFF + b * BN + t) * 4, g_wsq + tt * BN + t);
    };

    issue(0, 0);
    cp_commit();

    // ---- per-thread row state ----
    float xq[8], best[8];
    int bidx[8];
#pragma unroll
    for (int r = 0; r < 8; r++) {
        xq[r] = g_xsq[rowBase + ty + 16 * r];
        best[r] = 3.4e38f;
        bidx[r] = 0;
    }

    for (int tt = 0; tt < KT; tt++) {
        const int buf = tt & 1;
        if (tt + 1 < KT) { issue(tt + 1, buf ^ 1); cp_commit(); cp_wait1(); }
        else            { cp_wait0(); }
        __syncthreads();

        const float* wt  = sm + WT_OFF + buf * WT_SZ;
        const float* wqb = sm + WQ_OFF + buf * BN;

        ull acc[8][4];
#pragma unroll
        for (int r = 0; r < 8; r++)
#pragma unroll
            for (int c = 0; c < 4; c++) acc[r][c] = 0ULL;

#pragma unroll 2
        for (int d = 0; d < D_; d++) {
            const int key = d & 15;
            ull a2[8];
#pragma unroll
            for (int r = 0; r < 8; r++) a2[r] = pack2(xs[(ty + 16 * r) * XPAD + d]);
            ull b2[4];
#pragma unroll
            for (int c = 0; c < 4; c++) {
                int phys = (tx + 16 * c) ^ key;
                b2[c] = *(const ull*)(wt + d * BN + phys * 2);
            }
#pragma unroll
            for (int r = 0; r < 8; r++)
#pragma unroll
                for (int c = 0; c < 4; c++) fma2(acc[r][c], a2[r], b2[c]);
        }

        // ---- epilogue: distances + argmin (cols ascend within thread) ----
#pragma unroll
        for (int c = 0; c < 4; c++) {
            float wq0, wq1;
            unpack2(*(const ull*)(wqb + 2 * (tx + 16 * c)), wq0, wq1);
            int col0 = tt * BN + 2 * tx + 32 * c;
#pragma unroll
            for (int r = 0; r < 8; r++) {
                float p0, p1;
                unpack2(acc[r][c], p0, p1);
                float d0 = fmaf(-2.f, p0, xq[r] + wq0);
                float d1 = fmaf(-2.f, p1, xq[r] + wq1);
                if (d0 < best[r]) { best[r] = d0; bidx[r] = col0; }
                if (d1 < best[r]) { best[r] = d1; bidx[r] = col0 + 1; }
            }
        }
        __syncthreads();   // all reads of buf done before it is refilled
    }

    // ---- cross-thread argmin reduce (reuse wsT region) ----
    float* red_v = sm + WT_OFF;                    // 128*16 floats
    int*   red_i = (int*)(sm + WT_OFF + 2048);     // 128*16 ints
    int*   s_idx = (int*)(sm + WT_OFF + 4096);     // 128 ints
#pragma unroll
    for (int r = 0; r < 8; r++) {
        int row = ty + 16 * r;
        red_v[row * 16 + tx] = best[r];
        red_i[row * 16 + tx] = bidx[r];
    }
    __syncthreads();

    if (t < BM) {
        float bv = red_v[t * 16];
        int   bi = red_i[t * 16];
#pragma unroll
        for (int j = 1; j < 16; j++) {
            float v  = red_v[t * 16 + j];
            int   ii = red_i[t * 16 + j];
            if (v < bv || (v == bv && ii < bi)) { bv = v; bi = ii; }
        }
        s_idx[t] = bi;
        out[1 + (size_t)NROW * D_ + rowBase + t] = (float)bi;
    }
    __syncthreads();

    // ---- quantized gather + deterministic loss partial ----
    float lsum = 0.f;
#pragma unroll
    for (int i = 0; i < 32; i++) {
        int idx = t + i * NT;
        int r = idx >> 6, dc = idx & 63;
        float q = w[(size_t)s_idx[r] * D_ + dc];
        out[1 + (size_t)(rowBase + r) * D_ + dc] = q;
        float df = q - xs[r * XPAD + dc];
        lsum += df * df;
    }
#pragma unroll
    for (int o = 16; o > 0; o >>= 1) lsum += __shfl_down_sync(0xffffffffu, lsum, o);
    __shared__ float s_loss[8];
    if ((t & 31) == 0) s_loss[t >> 5] = lsum;
    __syncthreads();
    if (t == 0) {
        float s = 0.f;
#pragma unroll
        for (int wI = 0; wI < 8; wI++) s += s_loss[wI];
        g_block_loss[blockIdx.x] = s;
    }
}

// ---------------------------------------------------------------------------
__global__ void finalize_kernel(float* __restrict__ out) {
    __shared__ float sm[128];
    float s = (threadIdx.x < 128) ? g_block_loss[threadIdx.x] : 0.f;
    sm[threadIdx.x] = s;
    __syncthreads();
    for (int o = 64; o > 0; o >>= 1) {
        if (threadIdx.x < o) sm[threadIdx.x] += sm[threadIdx.x + o];
        __syncthreads();
    }
    if (threadIdx.x == 0) out[0] = 1.25f * sm[0] / (float)(NROW * D_);
}

// ---------------------------------------------------------------------------
extern "C" void kernel_launch(void* const* d_in, const int* in_sizes, int n_in,
                              void* d_out, int out_size) {
    const float* x = (const float*)d_in[0];
    const float* w = (const float*)d_in[1];
    float* out = (float*)d_out;

    prep_kernel<<<(NROW + 255) / 256, 256>>>(x, w);

    cudaFuncSetAttribute(vq_main, cudaFuncAttributeMaxDynamicSharedMemorySize, SMEM_BYTES);
    vq_main<<<NROW / BM, NT, SMEM_BYTES>>>(x, w, out);

    finalize_kernel<<<1, 128>>>(out);
}

// round 7
// speedup vs baseline: 1.0745x; 1.0653x over previous
#include <cuda_runtime.h>
#include <stdint.h>

#define D_    64
#define NROW  16384
#define KCB   8192
#define BM    128
#define BN    128
#define NT    256
#define KT    (KCB / BN)     // 64
#define CAP   256
#define PITCH 80             // bytes per int8 row in smem (64 data + 16 pad)

__device__ float    g_xsq[NROW];
__device__ float    g_wsq[KCB];
__device__ float    g_xl1[NROW];
__device__ float    g_xamax[NROW];
__device__ int      g_wamax_bits;     // idempotent atomicMax accumulators
__device__ int      g_wl1max_bits;
__device__ uint32_t g_xq8[NROW * 16]; // packed int8x4
__device__ uint32_t g_wq8[KCB * 16];
__device__ float    g_c2s[NROW];      // -2*sx*sw
__device__ float    g_m2B[NROW];      // candidate margin = 4*doterr
__device__ int      g_cnt[NROW];
__device__ int      g_cand[NROW * CAP];
__device__ float    g_rowloss[NROW];

// ---------------------------------------------------------------------------
__device__ __forceinline__ uint32_t smem_u32(const void* p) {
    uint32_t a;
    asm("{ .reg .u64 t; cvta.to.shared.u64 t, %1; cvt.u32.u64 %0, t; }" : "=r"(a) : "l"(p));
    return a;
}
__device__ __forceinline__ void cp16(uint32_t dst, const void* src) {
    asm volatile("cp.async.cg.shared.global [%0], [%1], 16;" :: "r"(dst), "l"(src));
}
__device__ __forceinline__ void cp_commit() { asm volatile("cp.async.commit_group;"); }
__device__ __forceinline__ void cp_wait1()  { asm volatile("cp.async.wait_group 1;"); }
__device__ __forceinline__ void cp_wait0()  { asm volatile("cp.async.wait_group 0;"); }

__device__ __forceinline__ int dp4a_(uint32_t a, uint32_t b, int c) {
    int d;
    asm("dp4a.s32.s32 %0, %1, %2, %3;" : "=r"(d) : "r"(a), "r"(b), "r"(c));
    return d;
}
__device__ __forceinline__ uint32_t pack4(float a, float b, float c, float d, float inv) {
    int q0 = __float2int_rn(a * inv) & 0xff;
    int q1 = __float2int_rn(b * inv) & 0xff;
    int q2 = __float2int_rn(c * inv) & 0xff;
    int q3 = __float2int_rn(d * inv) & 0xff;
    return (uint32_t)(q0 | (q1 << 8) | (q2 << 16) | (q3 << 24));
}

// ---------------------------------------------------------------------------
// prep1: warp-per-row norms / absmax / L1 (+ global maxes for w)
// ---------------------------------------------------------------------------
__global__ __launch_bounds__(256) void prep1_kernel(const float* __restrict__ x,
                                                    const float* __restrict__ w) {
    int gw = (blockIdx.x * 256 + threadIdx.x) >> 5;
    int lane = threadIdx.x & 31;
    const float* src = (gw < NROW) ? x : w;
    int row = (gw < NROW) ? gw : gw - NROW;
    if (gw >= NROW + KCB) return;

    float2 v = ((const float2*)(src + (size_t)row * D_))[lane];
    float s  = v.x * v.x + v.y * v.y;
    float l1 = fabsf(v.x) + fabsf(v.y);
    float am = fmaxf(fabsf(v.x), fabsf(v.y));
#pragma unroll
    for (int o = 16; o > 0; o >>= 1) {
        s  += __shfl_xor_sync(0xffffffffu, s, o);
        l1 += __shfl_xor_sync(0xffffffffu, l1, o);
        am  = fmaxf(am, __shfl_xor_sync(0xffffffffu, am, o));
    }
    if (lane == 0) {
        if (gw < NROW) {
            g_xsq[row] = s; g_xl1[row] = l1; g_xamax[row] = am; g_cnt[row] = 0;
        } else {
            g_wsq[row] = s;
            atomicMax(&g_wamax_bits, __float_as_int(am));   // am >= 0: bit-order ok
            atomicMax(&g_wl1max_bits, __float_as_int(l1));
        }
    }
}

// ---------------------------------------------------------------------------
// prep2: quantize to int8 (x: per-row scale, w: global scale) + margins
// ---------------------------------------------------------------------------
__global__ __launch_bounds__(256) void prep2_kernel(const float* __restrict__ x,
                                                    const float* __restrict__ w) {
    int row = blockIdx.x * 256 + threadIdx.x;
    if (row >= NROW + KCB) return;
    float wam = fmaxf(__int_as_float(g_wamax_bits), 1e-30f);
    float sw = wam * (1.f / 127.f);
    if (row < NROW) {
        float am = fmaxf(g_xamax[row], 1e-30f);
        float sx = am * (1.f / 127.f);
        float inv = 127.f / am;
        const float4* xr = (const float4*)(x + (size_t)row * D_);
#pragma unroll
        for (int q = 0; q < 16; q++) {
            float4 v = xr[q];
            g_xq8[row * 16 + q] = pack4(v.x, v.y, v.z, v.w, inv);
        }
        float l1w = __int_as_float(g_wl1max_bits);
        float doterr = 0.5f * sw * g_xl1[row] + 0.5f * sx * l1w + 16.f * sx * sw;
        g_c2s[row] = -2.f * sx * sw;
        g_m2B[row] = 4.f * doterr;
    } else {
        int r = row - NROW;
        float inv = 127.f / wam;
        const float4* wr = (const float4*)(w + (size_t)r * D_);
#pragma unroll
        for (int q = 0; q < 16; q++) {
            float4 v = wr[q];
            g_wq8[r * 16 + q] = pack4(v.x, v.y, v.z, v.w, inv);
        }
    }
}

// ---------------------------------------------------------------------------
// vq_filter: int8 dp4a distance GEMM + provable candidate filter
// 128x128 tiles, 256 threads, TM=8 x TN=8 per thread
// ---------------------------------------------------------------------------
__global__ __launch_bounds__(NT, 1) void vq_filter() {
    __shared__ uint8_t xsA[BM * PITCH];
    __shared__ uint8_t wsm[2][BM * PITCH];
    __shared__ float   wsqs[2][BN];

    const uint32_t sbA = smem_u32(xsA);
    const uint32_t sbW = smem_u32(wsm);
    const uint32_t sbQ = smem_u32(wsqs);

    const int t = threadIdx.x;
    const int tx = t & 15, ty = t >> 4;
    const int rowBase = blockIdx.x * BM;

    // A tile: 128 rows x 64B
#pragma unroll
    for (int i = 0; i < 2; i++) {
        int idx = t + i * NT;            // 512 x 16B
        int r = idx >> 2, q = idx & 3;
        cp16(sbA + r * PITCH + q * 16, g_xq8 + (size_t)(rowBase + r) * 16 + q * 4);
    }

    auto issue = [&](int tt, int b) {
#pragma unroll
        for (int i = 0; i < 2; i++) {
            int idx = t + i * NT;
            int r = idx >> 2, q = idx & 3;
            cp16(sbW + b * (BM * PITCH) + r * PITCH + q * 16,
                 g_wq8 + ((size_t)tt * BN + r) * 16 + q * 4);
        }
        if (t < 32) cp16(sbQ + b * (BN * 4) + t * 16, g_wsq + tt * BN + t * 4);
    };

    issue(0, 0);
    cp_commit();

    // per-thread row state (8 rows: ty + 16*r)
    float xqs[8], gmin[8], m2B[8], c2s[8];
    int rowid[8];
#pragma unroll
    for (int r = 0; r < 8; r++) {
        int row = rowBase + ty + 16 * r;
        rowid[r] = row;
        xqs[r] = g_xsq[row];
        m2B[r] = g_m2B[row];
        c2s[r] = g_c2s[row];
        gmin[r] = 3.4e38f;
    }

    for (int tt = 0; tt < KT; tt++) {
        const int buf = tt & 1;
        if (tt + 1 < KT) { issue(tt + 1, buf ^ 1); cp_commit(); cp_wait1(); }
        else             { cp_wait0(); }
        __syncthreads();

        const uint8_t* wt = wsm[buf];
        int acc[8][8];
#pragma unroll
        for (int r = 0; r < 8; r++)
#pragma unroll
            for (int c = 0; c < 8; c++) acc[r][c] = 0;

#pragma unroll 4
        for (int kq = 0; kq < 16; kq++) {
            uint32_t a4[8], b4[8];
#pragma unroll
            for (int r = 0; r < 8; r++)
                a4[r] = *(const uint32_t*)(xsA + (ty + 16 * r) * PITCH + kq * 4);
#pragma unroll
            for (int c = 0; c < 8; c++)
                b4[c] = *(const uint32_t*)(wt + (tx + 16 * c) * PITCH + kq * 4);
#pragma unroll
            for (int r = 0; r < 8; r++)
#pragma unroll
                for (int c = 0; c < 8; c++) acc[r][c] = dp4a_(a4[r], b4[c], acc[r][c]);
        }

        // epilogue: approx distances + provable-window candidate append
        const float* wqS = wsqs[buf];
#pragma unroll
        for (int c = 0; c < 8; c++) {
            int col = tx + 16 * c;
            float wq = wqS[col];
            int gcol = tt * BN + col;
#pragma unroll
            for (int r = 0; r < 8; r++) {
                float d = fmaf(c2s[r], (float)acc[r][c], xqs[r] + wq);
                if (d <= gmin[r] + m2B[r]) {
                    int p = atomicAdd(&g_cnt[rowid[r]], 1);
                    if (p < CAP) g_cand[rowid[r] * CAP + p] = gcol;
                }
                gmin[r] = fminf(gmin[r], d);
            }
        }
        // tighten running min across the 16 lanes sharing each row (same ty)
#pragma unroll
        for (int r = 0; r < 8; r++) {
            float v = gmin[r];
            v = fminf(v, __shfl_xor_sync(0xffffffffu, v, 1));
            v = fminf(v, __shfl_xor_sync(0xffffffffu, v, 2));
            v = fminf(v, __shfl_xor_sync(0xffffffffu, v, 4));
            v = fminf(v, __shfl_xor_sync(0xffffffffu, v, 8));
            gmin[r] = v;
        }
        __syncthreads();
    }
}

// ---------------------------------------------------------------------------
// rescore: exact fp32 argmin over candidates (warp per row), lowest-index ties
// out: [0]=loss, [1..N*D]=quantized, [1+N*D..]=indices (float)
// ---------------------------------------------------------------------------
__global__ __launch_bounds__(256) void rescore_kernel(const float* __restrict__ x,
                                                      const float* __restrict__ w,
                                                      float* __restrict__ out) {
    int row = (blockIdx.x * 256 + threadIdx.x) >> 5;
    int lane = threadIdx.x & 31;
    if (row >= NROW) return;

    int cnt = g_cnt[row];
    if (cnt > CAP) cnt = CAP;
    const int* cl = g_cand + (size_t)row * CAP;
    float2 xv = ((const float2*)(x + (size_t)row * D_))[lane];

    int bc;
    if (cnt == 1) {
        bc = cl[0];
    } else {
        float xq = g_xsq[row];
        float bd = 3.4e38f;
        bc = 0x7fffffff;
        for (int i = 0; i < cnt; i++) {
            int c0 = cl[i];
            float2 w0 = ((const float2*)(w + (size_t)c0 * D_))[lane];
            float p0 = xv.x * w0.x + xv.y * w0.y;
#pragma unroll
            for (int o = 16; o > 0; o >>= 1) p0 += __shfl_xor_sync(0xffffffffu, p0, o);
            float d0 = xq + g_wsq[c0] - 2.f * p0;
            if (d0 < bd || (d0 == bd && c0 < bc)) { bd = d0; bc = c0; }
        }
    }

    float2 wv = ((const float2*)(w + (size_t)bc * D_))[lane];
    float* qo = out + 1 + (size_t)row * D_ + lane * 2;   // 4B-aligned: scalar stores
    qo[0] = wv.x;
    qo[1] = wv.y;
    if (lane == 0) out[1 + (size_t)NROW * D_ + row] = (float)bc;

    float dx = wv.x - xv.x, dy = wv.y - xv.y;
    float l = dx * dx + dy * dy;
#pragma unroll
    for (int o = 16; o > 0; o >>= 1) l += __shfl_xor_sync(0xffffffffu, l, o);
    if (lane == 0) g_rowloss[row] = l;
}

// ---------------------------------------------------------------------------
__global__ void finalize_kernel(float* __restrict__ out) {
    __shared__ float sm[256];
    float s = 0.f;
    for (int i = threadIdx.x; i < NROW; i += 256) s += g_rowloss[i];
    sm[threadIdx.x] = s;
    __syncthreads();
    for (int o = 128; o > 0; o >>= 1) {
        if (threadIdx.x < o) sm[threadIdx.x] += sm[threadIdx.x + o];
        __syncthreads();
    }
    if (threadIdx.x == 0) out[0] = 1.25f * sm[0] / (float)(NROW * D_);
}

// ---------------------------------------------------------------------------
extern "C" void kernel_launch(void* const* d_in, const int* in_sizes, int n_in,
                              void* d_out, int out_size) {
    const float* x = (const float*)d_in[0];
    const float* w = (const float*)d_in[1];
    float* out = (float*)d_out;

    prep1_kernel<<<(NROW + KCB) / 8, 256>>>(x, w);
    prep2_kernel<<<(NROW + KCB + 255) / 256, 256>>>(x, w);
    vq_filter<<<NROW / BM, NT>>>();
    rescore_kernel<<<NROW / 8, 256>>>(x, w, out);
    finalize_kernel<<<1, 256>>>(out);
}

// round 8
// speedup vs baseline: 1.4447x; 1.3445x over previous
#include <cuda_runtime.h>
#include <stdint.h>

#define D_    64
#define NROW  16384
#define KCB   8192
#define BM    64
#define BN    128
#define NT    256
#define KT    (KCB / BN)     // 64
#define CAP   256
#define PITCH 80             // bytes per int8 row in smem (64 data + 16 pad, 16B-aligned)

__device__ float    g_xsq[NROW];
__device__ float    g_wsq[KCB];
__device__ float    g_xl1[NROW];
__device__ float    g_xamax[NROW];
__device__ int      g_wamax_bits;
__device__ int      g_wl1max_bits;
__device__ uint32_t g_xq8[NROW * 16]; // packed int8x4
__device__ uint32_t g_wq8[KCB * 16];
__device__ float    g_c2s[NROW];      // -2*sx*sw
__device__ float    g_m2B[NROW];      // candidate margin = 4*doterr
__device__ int      g_cnt[NROW];
__device__ int      g_cand[NROW * CAP];
__device__ float    g_rowloss[NROW];

// ---------------------------------------------------------------------------
__device__ __forceinline__ uint32_t smem_u32(const void* p) {
    uint32_t a;
    asm("{ .reg .u64 t; cvta.to.shared.u64 t, %1; cvt.u32.u64 %0, t; }" : "=r"(a) : "l"(p));
    return a;
}
__device__ __forceinline__ void cp16(uint32_t dst, const void* src) {
    asm volatile("cp.async.cg.shared.global [%0], [%1], 16;" :: "r"(dst), "l"(src));
}
__device__ __forceinline__ void cp_commit() { asm volatile("cp.async.commit_group;"); }
__device__ __forceinline__ void cp_wait1()  { asm volatile("cp.async.wait_group 1;"); }
__device__ __forceinline__ void cp_wait0()  { asm volatile("cp.async.wait_group 0;"); }

__device__ __forceinline__ int dp4a_(uint32_t a, uint32_t b, int c) {
    int d;
    asm("dp4a.s32.s32 %0, %1, %2, %3;" : "=r"(d) : "r"(a), "r"(b), "r"(c));
    return d;
}
__device__ __forceinline__ uint32_t pack4(float a, float b, float c, float d, float inv) {
    int q0 = __float2int_rn(a * inv) & 0xff;
    int q1 = __float2int_rn(b * inv) & 0xff;
    int q2 = __float2int_rn(c * inv) & 0xff;
    int q3 = __float2int_rn(d * inv) & 0xff;
    return (uint32_t)(q0 | (q1 << 8) | (q2 << 16) | (q3 << 24));
}

// ---------------------------------------------------------------------------
// prep1: warp-per-row norms / absmax / L1 (+ global maxes for w)
// ---------------------------------------------------------------------------
__global__ __launch_bounds__(256) void prep1_kernel(const float* __restrict__ x,
                                                    const float* __restrict__ w) {
    int gw = (blockIdx.x * 256 + threadIdx.x) >> 5;
    int lane = threadIdx.x & 31;
    if (gw >= NROW + KCB) return;
    const float* src = (gw < NROW) ? x : w;
    int row = (gw < NROW) ? gw : gw - NROW;

    float2 v = ((const float2*)(src + (size_t)row * D_))[lane];
    float s  = v.x * v.x + v.y * v.y;
    float l1 = fabsf(v.x) + fabsf(v.y);
    float am = fmaxf(fabsf(v.x), fabsf(v.y));
#pragma unroll
    for (int o = 16; o > 0; o >>= 1) {
        s  += __shfl_xor_sync(0xffffffffu, s, o);
        l1 += __shfl_xor_sync(0xffffffffu, l1, o);
        am  = fmaxf(am, __shfl_xor_sync(0xffffffffu, am, o));
    }
    if (lane == 0) {
        if (gw < NROW) {
            g_xsq[row] = s; g_xl1[row] = l1; g_xamax[row] = am; g_cnt[row] = 0;
        } else {
            g_wsq[row] = s;
            atomicMax(&g_wamax_bits, __float_as_int(am));
            atomicMax(&g_wl1max_bits, __float_as_int(l1));
        }
    }
}

// ---------------------------------------------------------------------------
// prep2: quantize to int8 (x: per-row scale, w: global scale) + margins
// ---------------------------------------------------------------------------
__global__ __launch_bounds__(256) void prep2_kernel(const float* __restrict__ x,
                                                    const float* __restrict__ w) {
    int row = blockIdx.x * 256 + threadIdx.x;
    if (row >= NROW + KCB) return;
    float wam = fmaxf(__int_as_float(g_wamax_bits), 1e-30f);
    float sw = wam * (1.f / 127.f);
    if (row < NROW) {
        float am = fmaxf(g_xamax[row], 1e-30f);
        float sx = am * (1.f / 127.f);
        float inv = 127.f / am;
        const float4* xr = (const float4*)(x + (size_t)row * D_);
#pragma unroll
        for (int q = 0; q < 16; q++) {
            float4 v = xr[q];
            g_xq8[row * 16 + q] = pack4(v.x, v.y, v.z, v.w, inv);
        }
        float l1w = __int_as_float(g_wl1max_bits);
        float doterr = 0.5f * sw * g_xl1[row] + 0.5f * sx * l1w + 16.f * sx * sw;
        g_c2s[row] = -2.f * sx * sw;
        g_m2B[row] = 4.f * doterr;
    } else {
        int r = row - NROW;
        float inv = 127.f / wam;
        const float4* wr = (const float4*)(w + (size_t)r * D_);
#pragma unroll
        for (int q = 0; q < 16; q++) {
            float4 v = wr[q];
            g_wq8[r * 16 + q] = pack4(v.x, v.y, v.z, v.w, inv);
        }
    }
}

// ---------------------------------------------------------------------------
// vq_filter: int8 dp4a distance GEMM + provable candidate filter
// 64x128 tiles, 256 threads, TM=4 x TN=8, LDS.64 operand loads, 2 CTAs/SM
// ---------------------------------------------------------------------------
__global__ __launch_bounds__(NT, 2) void vq_filter() {
    __shared__ uint8_t xsA[BM * PITCH];          // 5120 B
    __shared__ uint8_t wsm[2][BN * PITCH];       // 2 x 10240 B
    __shared__ float   wsqs[2][BN];              // 2 x 512 B

    const uint32_t sbA = smem_u32(xsA);
    const uint32_t sbW = smem_u32(wsm);
    const uint32_t sbQ = smem_u32(wsqs);

    const int t = threadIdx.x;
    const int tx = t & 15, ty = t >> 4;
    const int rowBase = blockIdx.x * BM;

    // A tile: 64 rows x 64B = 256 x 16B (one cp16 per thread)
    {
        int r = t >> 2, q = t & 3;
        cp16(sbA + r * PITCH + q * 16, g_xq8 + (size_t)(rowBase + r) * 16 + q * 4);
    }

    auto issue = [&](int tt, int b) {
#pragma unroll
        for (int i = 0; i < 2; i++) {
            int idx = t + i * NT;                // 512 x 16B
            int r = idx >> 2, q = idx & 3;
            cp16(sbW + b * (BN * PITCH) + r * PITCH + q * 16,
                 g_wq8 + ((size_t)tt * BN + r) * 16 + q * 4);
        }
        if (t < 32) cp16(sbQ + b * (BN * 4) + t * 16, g_wsq + tt * BN + t * 4);
    };

    issue(0, 0);
    cp_commit();

    // per-thread row state (4 rows: ty + 16*r)
    float xqs[4], gmin[4], m2B[4], c2s[4];
    int rowid[4];
#pragma unroll
    for (int r = 0; r < 4; r++) {
        int row = rowBase + ty + 16 * r;
        rowid[r] = row;
        xqs[r] = g_xsq[row];
        m2B[r] = g_m2B[row];
        c2s[r] = g_c2s[row];
        gmin[r] = 3.4e38f;
    }

    for (int tt = 0; tt < KT; tt++) {
        const int buf = tt & 1;
        if (tt + 1 < KT) { issue(tt + 1, buf ^ 1); cp_commit(); cp_wait1(); }
        else             { cp_wait0(); }
        __syncthreads();

        const uint8_t* wt = wsm[buf];
        int acc[4][8];
#pragma unroll
        for (int r = 0; r < 4; r++)
#pragma unroll
            for (int c = 0; c < 8; c++) acc[r][c] = 0;

#pragma unroll
        for (int kq2 = 0; kq2 < 8; kq2++) {      // 8 bytes of k per step
            uint2 a2[4], b2[8];
#pragma unroll
            for (int r = 0; r < 4; r++)
                a2[r] = *(const uint2*)(xsA + (ty + 16 * r) * PITCH + kq2 * 8);
#pragma unroll
            for (int c = 0; c < 8; c++)
                b2[c] = *(const uint2*)(wt + (tx + 16 * c) * PITCH + kq2 * 8);
#pragma unroll
            for (int r = 0; r < 4; r++)
#pragma unroll
                for (int c = 0; c < 8; c++) {
                    acc[r][c] = dp4a_(a2[r].x, b2[c].x, acc[r][c]);
                    acc[r][c] = dp4a_(a2[r].y, b2[c].y, acc[r][c]);
                }
        }

        // epilogue: approx distances + provable-window candidate append
        const float* wqS = wsqs[buf];
#pragma unroll
        for (int c = 0; c < 8; c++) {
            int col = tx + 16 * c;
            float wq = wqS[col];
            int gcol = tt * BN + col;
#pragma unroll
            for (int r = 0; r < 4; r++) {
                float d = fmaf(c2s[r], (float)acc[r][c], xqs[r] + wq);
                if (d <= gmin[r] + m2B[r]) {
                    int p = atomicAdd(&g_cnt[rowid[r]], 1);
                    if (p < CAP) g_cand[rowid[r] * CAP + p] = gcol;
                }
                gmin[r] = fminf(gmin[r], d);
            }
        }
        // tighten running min across the 16 lanes sharing each row
#pragma unroll
        for (int r = 0; r < 4; r++) {
            float v = gmin[r];
            v = fminf(v, __shfl_xor_sync(0xffffffffu, v, 1));
            v = fminf(v, __shfl_xor_sync(0xffffffffu, v, 2));
            v = fminf(v, __shfl_xor_sync(0xffffffffu, v, 4));
            v = fminf(v, __shfl_xor_sync(0xffffffffu, v, 8));
            gmin[r] = v;
        }
        __syncthreads();
    }
}

// ---------------------------------------------------------------------------
// rescore: exact fp32 argmin over candidates (warp per row), lowest-index ties
// out: [0]=loss, [1..N*D]=quantized, [1+N*D..]=indices (float)
// ---------------------------------------------------------------------------
__global__ __launch_bounds__(256) void rescore_kernel(const float* __restrict__ x,
                                                      const float* __restrict__ w,
                                                      float* __restrict__ out) {
    int row = (blockIdx.x * 256 + threadIdx.x) >> 5;
    int lane = threadIdx.x & 31;
    if (row >= NROW) return;

    int cnt = g_cnt[row];
    if (cnt > CAP) cnt = CAP;
    const int* cl = g_cand + (size_t)row * CAP;
    float2 xv = ((const float2*)(x + (size_t)row * D_))[lane];

    int bc;
    if (cnt == 1) {
        bc = cl[0];
    } else {
        float xq = g_xsq[row];
        float bd = 3.4e38f;
        bc = 0x7fffffff;
        int i = 0;
        for (; i + 2 <= cnt; i += 2) {
            int c0 = cl[i], c1 = cl[i + 1];
            float2 w0 = ((const float2*)(w + (size_t)c0 * D_))[lane];
            float2 w1 = ((const float2*)(w + (size_t)c1 * D_))[lane];
            float p0 = xv.x * w0.x + xv.y * w0.y;
            float p1 = xv.x * w1.x + xv.y * w1.y;
#pragma unroll
            for (int o = 16; o > 0; o >>= 1) {
                p0 += __shfl_xor_sync(0xffffffffu, p0, o);
                p1 += __shfl_xor_sync(0xffffffffu, p1, o);
            }
            float d0 = xq + g_wsq[c0] - 2.f * p0;
            float d1 = xq + g_wsq[c1] - 2.f * p1;
            if (d0 < bd || (d0 == bd && c0 < bc)) { bd = d0; bc = c0; }
            if (d1 < bd || (d1 == bd && c1 < bc)) { bd = d1; bc = c1; }
        }
        if (i < cnt) {
            int c0 = cl[i];
            float2 w0 = ((const float2*)(w + (size_t)c0 * D_))[lane];
            float p0 = xv.x * w0.x + xv.y * w0.y;
#pragma unroll
            for (int o = 16; o > 0; o >>= 1) p0 += __shfl_xor_sync(0xffffffffu, p0, o);
            float d0 = xq + g_wsq[c0] - 2.f * p0;
            if (d0 < bd || (d0 == bd && c0 < bc)) { bd = d0; bc = c0; }
        }
    }

    float2 wv = ((const float2*)(w + (size_t)bc * D_))[lane];
    float* qo = out + 1 + (size_t)row * D_ + lane * 2;   // 4B-aligned: scalar stores
    qo[0] = wv.x;
    qo[1] = wv.y;
    if (lane == 0) out[1 + (size_t)NROW * D_ + row] = (float)bc;

    float dx = wv.x - xv.x, dy = wv.y - xv.y;
    float l = dx * dx + dy * dy;
#pragma unroll
    for (int o = 16; o > 0; o >>= 1) l += __shfl_xor_sync(0xffffffffu, l, o);
    if (lane == 0) g_rowloss[row] = l;
}

// ---------------------------------------------------------------------------
__global__ void finalize_kernel(float* __restrict__ out) {
    __shared__ float sm[256];
    float s = 0.f;
    for (int i = threadIdx.x; i < NROW; i += 256) s += g_rowloss[i];
    sm[threadIdx.x] = s;
    __syncthreads();
    for (int o = 128; o > 0; o >>= 1) {
        if (threadIdx.x < o) sm[threadIdx.x] += sm[threadIdx.x + o];
        __syncthreads();
    }
    if (threadIdx.x == 0) out[0] = 1.25f * sm[0] / (float)(NROW * D_);
}

// ---------------------------------------------------------------------------
extern "C" void kernel_launch(void* const* d_in, const int* in_sizes, int n_in,
                              void* d_out, int out_size) {
    const float* x = (const float*)d_in[0];
    const float* w = (const float*)d_in[1];
    float* out = (float*)d_out;

    prep1_kernel<<<(NROW + KCB) / 8, 256>>>(x, w);
    prep2_kernel<<<(NROW + KCB + 255) / 256, 256>>>(x, w);
    vq_filter<<<NROW / BM, NT>>>();
    rescore_kernel<<<NROW / 8, 256>>>(x, w, out);
    finalize_kernel<<<1, 256>>>(out);
}